// round 5
// baseline (speedup 1.0000x reference)
#include <cuda_runtime.h>

// Spatial GCN on a 24x24 grid: adj = D^-1 A + I (4-neighbor grid) => 5-point
// stencil with analytic 1/deg(neighbor) in {1/2, 1/3, 1/4}. Then elementwise
// weight, BatchNorm2d (batch stats), LeakyReLU(0.2).
//
// R5: chunk-linear mapping + U=4 image loop per thread. Coefficients/index
// math (depend only on chunk position) amortized over 4 images; inner loop is
// pure coalesced LDG + FMA with high MLP.

#define B_   64
#define C_   512
#define NN   576
#define BN_EPS 1e-4f
#define SLOPE  0.2f

#define TPB  288     // 2 chunk-slots of 144
#define U_   4       // images per thread -> 8 images per block

__device__ float g_psum[C_ * B_];
__device__ float g_psq [C_ * B_];
__device__ float g_scale[C_];
__device__ float g_shift[C_];

__device__ __forceinline__ float invd(int d) {
    // d in {2,3,4}
    return d == 4 ? 0.25f : (d == 3 ? (1.0f / 3.0f) : 0.5f);
}

template <bool STATS>
__global__ __launch_bounds__(TPB) void k_main(const float* __restrict__ x,
                                              const float* __restrict__ w,
                                              float* __restrict__ out) {
    __shared__ float ps1[2 * U_ * 144], ps2[2 * U_ * 144];
    __shared__ float qs1[128], qs2[128];

    const int tid = threadIdx.x;
    const int in1 = tid >= 144;                  // chunk-slot (0/1)
    const int r   = tid - 144 * in1;             // chunk within image, 0..143
    const int i   = r / 6;                       // row 0..23
    const int q   = r - 6 * i;                   // float4 chunk in row, 0..5
    const int g0  = blockIdx.x * (2 * U_) + in1 * U_;  // first image
    const int c0  = g0 & (C_ - 1);               // channels consecutive, no wrap
    const size_t off0 = (size_t)g0 * NN + r * 4;

    // ---- stencil coefficients (once per 4 images) ----
    const int rti = (i > 0) + (i < 23);
    const int rtu = (i > 1) + 1;                 // rowterm(i-1), valid iff i>0
    const int rtd = 1 + (i < 22);                // rowterm(i+1), valid iff i<23
    const float cHi = invd(rti + 2);
    const float cHe = invd(rti + 1);
    const float cUi = invd(rtu + 2), cUe = invd(rtu + 1);
    const float cDi = invd(rtd + 2), cDe = invd(rtd + 1);

    const bool q0 = (q == 0), q5 = (q == 5);
    const bool hasU = (i > 0), hasD = (i < 23);
    const float cL0 = q0 ? 0.0f : cHi;
    const float cL1 = q0 ? cHe  : cHi;
    const float cR2 = q5 ? cHe  : cHi;
    const float cR3 = q5 ? 0.0f : cHi;
    const float vU = hasU ? 1.0f : 0.0f;
    const float vD = hasD ? 1.0f : 0.0f;
    const float cU0 = vU * (q0 ? cUe : cUi), cUm = vU * cUi, cU3 = vU * (q5 ? cUe : cUi);
    const float cD0 = vD * (q0 ? cDe : cDi), cDm = vD * cDi, cD3 = vD * (q5 ? cDe : cDi);

    float a1[U_], a2[U_];

    #pragma unroll
    for (int u = 0; u < U_; u++) {
        const float* xp = x + off0 + u * NN;
        const float4 ct = *(const float4*)xp;
        float4 up = make_float4(0.f, 0.f, 0.f, 0.f);
        float4 dn = make_float4(0.f, 0.f, 0.f, 0.f);
        if (hasU) up = *(const float4*)(xp - 24);
        if (hasD) dn = *(const float4*)(xp + 24);
        const float lf = q0 ? 0.0f : __ldg(xp - 1);
        const float rg = q5 ? 0.0f : __ldg(xp + 4);
        const float4 wv = __ldg((const float4*)(w + (c0 + u) * NN + r * 4));

        const float s0 = ct.x + cL0 * lf   + cHi * ct.y + cU0 * up.x + cD0 * dn.x;
        const float s1 = ct.y + cL1 * ct.x + cHi * ct.z + cUm * up.y + cDm * dn.y;
        const float s2 = ct.z + cHi * ct.y + cR2 * ct.w + cUm * up.z + cDm * dn.z;
        const float s3 = ct.w + cHi * ct.z + cR3 * rg   + cU3 * up.w + cD3 * dn.w;

        const float y0 = s0 * wv.x, y1 = s1 * wv.y, y2 = s2 * wv.z, y3 = s3 * wv.w;

        if (STATS) {
            a1[u] = (y0 + y1) + (y2 + y3);
            a2[u] = (y0 * y0 + y1 * y1) + (y2 * y2 + y3 * y3);
        } else {
            const float sc = g_scale[c0 + u], sh = g_shift[c0 + u];
            float n0 = fmaf(y0, sc, sh), n1 = fmaf(y1, sc, sh);
            float n2 = fmaf(y2, sc, sh), n3 = fmaf(y3, sc, sh);
            n0 = (n0 >= 0.f) ? n0 : SLOPE * n0;
            n1 = (n1 >= 0.f) ? n1 : SLOPE * n1;
            n2 = (n2 >= 0.f) ? n2 : SLOPE * n2;
            n3 = (n3 >= 0.f) ? n3 : SLOPE * n3;
            *(float4*)(out + off0 + u * NN) = make_float4(n0, n1, n2, n3);
        }
    }

    if (STATS) {
        #pragma unroll
        for (int u = 0; u < U_; u++) {
            ps1[(in1 * U_ + u) * 144 + r] = a1[u];
            ps2[(in1 * U_ + u) * 144 + r] = a2[u];
        }
        __syncthreads();
        // stage 1: 128 threads sum 9 consecutive partials (144/9=16 groups per
        // image; groups never straddle an image)
        if (tid < 128) {
            float a = 0.f, b = 0.f;
            #pragma unroll
            for (int k = 0; k < 9; k++) { a += ps1[tid * 9 + k]; b += ps2[tid * 9 + k]; }
            qs1[tid] = a; qs2[tid] = b;
        }
        __syncthreads();
        // stage 2: 8 threads (one per image) sum 16 group partials
        if (tid < 2 * U_) {
            float a = 0.f, b = 0.f;
            #pragma unroll
            for (int k = 0; k < 16; k++) { a += qs1[tid * 16 + k]; b += qs2[tid * 16 + k]; }
            const int bc = blockIdx.x * (2 * U_) + tid;
            const int bb = bc >> 9, cc = bc & (C_ - 1);
            g_psum[cc * B_ + bb] = a;
            g_psq [cc * B_ + bb] = b;
        }
    }
}

__global__ void k_finalize(const float* __restrict__ gamma,
                           const float* __restrict__ beta) {
    const int c = threadIdx.x;   // 512 threads
    float s1 = 0.0f, s2 = 0.0f;
    #pragma unroll 8
    for (int b = 0; b < B_; b++) {
        s1 += g_psum[c * B_ + b];
        s2 += g_psq [c * B_ + b];
    }
    const float invn = 1.0f / (float)(B_ * NN);
    const float mean = s1 * invn;
    const float var  = s2 * invn - mean * mean;
    const float sc = gamma[c] * rsqrtf(var + BN_EPS);
    g_scale[c] = sc;
    g_shift[c] = beta[c] - mean * sc;
}

extern "C" void kernel_launch(void* const* d_in, const int* in_sizes, int n_in,
                              void* d_out, int out_size) {
    const float* x     = (const float*)d_in[0];   // [64,512,24,24]
    // d_in[1] = adj (unused: grid structure exploited analytically)
    const float* w     = (const float*)d_in[2];   // [512,576]
    const float* gamma = (const float*)d_in[3];   // [512]
    const float* beta  = (const float*)d_in[4];   // [512]
    float* out = (float*)d_out;

    const int nblk = (B_ * C_) / (2 * U_);        // 4096 blocks, 8 images each
    k_main<true ><<<nblk, TPB>>>(x, w, out);
    k_finalize<<<1, C_>>>(gamma, beta);
    k_main<false><<<nblk, TPB>>>(x, w, out);
}

// round 6
// speedup vs baseline: 1.0657x; 1.0657x over previous
#include <cuda_runtime.h>

// Spatial GCN on a 24x24 grid: adj = D^-1 A + I (4-neighbor grid) => 5-point
// stencil with analytic 1/deg(neighbor) in {1/2, 1/3, 1/4}. Then elementwise
// weight, BatchNorm2d (batch stats), LeakyReLU(0.2).
//
// R6: chunk-linear mapping; neighbor values come from WARP SHUFFLES of the
// center float4 (lane-6 = row above, lane-1 = left) with predicated boundary
// fallback loads. U=2 image loop; BN finalize folded into pass 2.

#define B_   64
#define C_   512
#define NN   576
#define BN_EPS 1e-4f
#define SLOPE  0.2f

#define TPB  288     // 2 chunk-slots of 144 (9 full warps)
#define U_   2
#define IPB  (2*U_)  // images per block = 4

__device__ float g_psum[C_ * B_];
__device__ float g_psq [C_ * B_];

__device__ __forceinline__ float invd(int d) {
    // d in {2,3,4}
    return d == 4 ? 0.25f : (d == 3 ? (1.0f / 3.0f) : 0.5f);
}

template <bool STATS>
__global__ __launch_bounds__(TPB, 5) void k_main(const float* __restrict__ x,
                                                 const float* __restrict__ w,
                                                 const float* __restrict__ gamma,
                                                 const float* __restrict__ beta,
                                                 float* __restrict__ out) {
    __shared__ float ps1[IPB * 144], ps2[IPB * 144];
    __shared__ float qs1[64], qs2[64];
    __shared__ float sscale[IPB], sshift[IPB];

    const int tid  = threadIdx.x;
    const int lane = tid & 31;
    const int slot = tid >= 144;
    const int r    = tid - 144 * slot;           // chunk 0..143
    const int i    = r / 6;                      // row
    const int q    = r - 6 * i;                  // chunk-in-row
    const int g0   = blockIdx.x * IPB + slot * U_;
    const int c0   = g0 & (C_ - 1);
    const size_t off0 = (size_t)g0 * NN + r * 4;
    const unsigned FULL = 0xFFFFFFFFu;

    // ---- pass 2: per-block BN finalize for this block's channels ----
    if (!STATS) {
        if (tid < IPB) {
            const int bc = blockIdx.x * IPB + tid;
            const int cc = bc & (C_ - 1);
            const float4* p1 = (const float4*)(g_psum + cc * B_);
            const float4* p2 = (const float4*)(g_psq  + cc * B_);
            float s1 = 0.f, s2 = 0.f;
            #pragma unroll
            for (int k = 0; k < 16; k++) {
                float4 a = p1[k], b = p2[k];
                s1 += (a.x + a.y) + (a.z + a.w);
                s2 += (b.x + b.y) + (b.z + b.w);
            }
            const float invn = 1.0f / 36864.0f;      // 1/(B*NN)
            const float mean = s1 * invn;
            const float var  = s2 * invn - mean * mean;
            const float sc = gamma[cc] * rsqrtf(var + BN_EPS);
            sscale[tid] = sc;
            sshift[tid] = beta[cc] - mean * sc;
        }
        __syncthreads();
    }

    // ---- stencil coefficients (chunk-position only) ----
    const int rti = (i > 0) + (i < 23);
    const int rtu = (i > 1) + 1;                 // rowterm(i-1), valid iff i>0
    const int rtd = 1 + (i < 22);                // rowterm(i+1), valid iff i<23
    const float cHi = invd(rti + 2);
    const float cHe = invd(rti + 1);
    const float cUi = invd(rtu + 2), cUe = invd(rtu + 1);
    const float cDi = invd(rtd + 2), cDe = invd(rtd + 1);

    const bool q0 = (q == 0), q5 = (q == 5);
    const bool hasU = (i > 0), hasD = (i < 23);
    const float cL0 = q0 ? 0.0f : cHi;
    const float cL1 = q0 ? cHe  : cHi;
    const float cR2 = q5 ? cHe  : cHi;
    const float cR3 = q5 ? 0.0f : cHi;
    const float vU = hasU ? 1.0f : 0.0f;
    const float vD = hasD ? 1.0f : 0.0f;
    const float cU0 = vU * (q0 ? cUe : cUi), cUm = vU * cUi, cU3 = vU * (q5 ? cUe : cUi);
    const float cD0 = vD * (q0 ? cDe : cDi), cDm = vD * cDi, cD3 = vD * (q5 ? cDe : cDi);

    const bool fbU = hasU && (lane < 6);         // up crosses warp boundary
    const bool fbD = hasD && (lane >= 26);       // down crosses warp boundary
    const bool fbL = (!q0) && (lane == 0);
    const bool fbR = (!q5) && (lane == 31);

    float a1[U_], a2[U_];

    #pragma unroll
    for (int u = 0; u < U_; u++) {
        const float* xp = x + off0 + u * NN;
        const float4 ct = *(const float4*)xp;
        const float4 wv = __ldg((const float4*)(w + (c0 + u) * NN + r * 4));

        // neighbors via shuffle (masked positions multiply by 0-coeff;
        // shuffled garbage there is another lane's finite ct value)
        float4 up, dn;
        up.x = __shfl_up_sync(FULL, ct.x, 6);
        up.y = __shfl_up_sync(FULL, ct.y, 6);
        up.z = __shfl_up_sync(FULL, ct.z, 6);
        up.w = __shfl_up_sync(FULL, ct.w, 6);
        if (fbU) up = *(const float4*)(xp - 24);
        dn.x = __shfl_down_sync(FULL, ct.x, 6);
        dn.y = __shfl_down_sync(FULL, ct.y, 6);
        dn.z = __shfl_down_sync(FULL, ct.z, 6);
        dn.w = __shfl_down_sync(FULL, ct.w, 6);
        if (fbD) dn = *(const float4*)(xp + 24);
        float lf = __shfl_up_sync(FULL, ct.w, 1);
        if (fbL) lf = __ldg(xp - 1);
        float rg = __shfl_down_sync(FULL, ct.x, 1);
        if (fbR) rg = __ldg(xp + 4);

        const float s0 = ct.x + cL0 * lf   + cHi * ct.y + cU0 * up.x + cD0 * dn.x;
        const float s1 = ct.y + cL1 * ct.x + cHi * ct.z + cUm * up.y + cDm * dn.y;
        const float s2 = ct.z + cHi * ct.y + cR2 * ct.w + cUm * up.z + cDm * dn.z;
        const float s3 = ct.w + cHi * ct.z + cR3 * rg   + cU3 * up.w + cD3 * dn.w;

        const float y0 = s0 * wv.x, y1 = s1 * wv.y, y2 = s2 * wv.z, y3 = s3 * wv.w;

        if (STATS) {
            a1[u] = (y0 + y1) + (y2 + y3);
            a2[u] = (y0 * y0 + y1 * y1) + (y2 * y2 + y3 * y3);
        } else {
            const float sc = sscale[slot * U_ + u], sh = sshift[slot * U_ + u];
            float n0 = fmaf(y0, sc, sh), n1 = fmaf(y1, sc, sh);
            float n2 = fmaf(y2, sc, sh), n3 = fmaf(y3, sc, sh);
            n0 = (n0 >= 0.f) ? n0 : SLOPE * n0;
            n1 = (n1 >= 0.f) ? n1 : SLOPE * n1;
            n2 = (n2 >= 0.f) ? n2 : SLOPE * n2;
            n3 = (n3 >= 0.f) ? n3 : SLOPE * n3;
            *(float4*)(out + off0 + u * NN) = make_float4(n0, n1, n2, n3);
        }
    }

    if (STATS) {
        #pragma unroll
        for (int u = 0; u < U_; u++) {
            ps1[(slot * U_ + u) * 144 + r] = a1[u];
            ps2[(slot * U_ + u) * 144 + r] = a2[u];
        }
        __syncthreads();
        // stage 1: 64 threads sum 9 consecutive partials (16 groups/image,
        // groups never straddle an image)
        if (tid < 64) {
            float a = 0.f, b = 0.f;
            #pragma unroll
            for (int k = 0; k < 9; k++) { a += ps1[tid * 9 + k]; b += ps2[tid * 9 + k]; }
            qs1[tid] = a; qs2[tid] = b;
        }
        __syncthreads();
        // stage 2: one thread per image sums its 16 group partials
        if (tid < IPB) {
            float a = 0.f, b = 0.f;
            #pragma unroll
            for (int k = 0; k < 16; k++) { a += qs1[tid * 16 + k]; b += qs2[tid * 16 + k]; }
            const int bc = blockIdx.x * IPB + tid;
            const int bb = bc >> 9, cc = bc & (C_ - 1);
            g_psum[cc * B_ + bb] = a;
            g_psq [cc * B_ + bb] = b;
        }
    }
}

extern "C" void kernel_launch(void* const* d_in, const int* in_sizes, int n_in,
                              void* d_out, int out_size) {
    const float* x     = (const float*)d_in[0];   // [64,512,24,24]
    // d_in[1] = adj (unused: grid structure exploited analytically)
    const float* w     = (const float*)d_in[2];   // [512,576]
    const float* gamma = (const float*)d_in[3];   // [512]
    const float* beta  = (const float*)d_in[4];   // [512]
    float* out = (float*)d_out;

    const int nblk = (B_ * C_) / IPB;             // 8192 blocks, 4 images each
    k_main<true ><<<nblk, TPB>>>(x, w, gamma, beta, out);
    k_main<false><<<nblk, TPB>>>(x, w, gamma, beta, out);
}

// round 8
// speedup vs baseline: 1.5589x; 1.4628x over previous
#include <cuda_runtime.h>

// Spatial GCN on a 24x24 grid: adj = D^-1 A + I (4-neighbor grid) => 5-point
// stencil with analytic 1/deg(neighbor) in {1/2, 1/3, 1/4}. Then elementwise
// weight, BatchNorm2d (batch stats), LeakyReLU(0.2).
//
// R7 (resubmit after infra failure): pass1 computes y (smem-staged stencil,
// batched center loads), writes y to out and reduces BN partials. finalize ->
// scale/shift. pass2 is a pure streaming normalize+LeakyReLU over out in place.

#define B_   64
#define C_   512
#define NN   576
#define BN_EPS 1e-4f
#define SLOPE  0.2f

#define TPB  288     // 2 chunk-slots of 144
#define U_   4
#define IPB  (2*U_)  // 8 images per block

__device__ float g_psum[C_ * B_];
__device__ float g_psq [C_ * B_];
__device__ float g_scale[C_];
__device__ float g_shift[C_];

__device__ __forceinline__ float invd(int d) {
    // d in {2,3,4}
    return d == 4 ? 0.25f : (d == 3 ? (1.0f / 3.0f) : 0.5f);
}

// ---------------- Pass 1: stencil*weight -> y, stats ----------------
__global__ __launch_bounds__(TPB, 4) void k_pass1(const float* __restrict__ x,
                                                  const float* __restrict__ w,
                                                  float* __restrict__ out) {
    __shared__ float xs[IPB * NN];                 // 18 KB staged images
    __shared__ float ps1[IPB * 144], ps2[IPB * 144];
    __shared__ float qs1[128], qs2[128];

    const int tid  = threadIdx.x;
    const int slot = tid >= 144;
    const int r    = tid - 144 * slot;             // chunk 0..143
    const int i    = r / 6;                        // row
    const int q    = r - 6 * i;                    // chunk-in-row
    const int g0   = blockIdx.x * IPB + slot * U_;
    const int c0   = g0 & (C_ - 1);
    const size_t off0 = (size_t)g0 * NN + r * 4;

    // batched center loads (MLP=4), then stage to smem
    float4 ct[U_];
    #pragma unroll
    for (int u = 0; u < U_; u++)
        ct[u] = *(const float4*)(x + off0 + u * NN);
    #pragma unroll
    for (int u = 0; u < U_; u++)
        *(float4*)(xs + (slot * U_ + u) * NN + r * 4) = ct[u];
    __syncthreads();

    // stencil coefficients (chunk-position only)
    const int rti = (i > 0) + (i < 23);
    const int rtu = (i > 1) + 1;                   // rowterm(i-1), valid iff i>0
    const int rtd = 1 + (i < 22);                  // rowterm(i+1), valid iff i<23
    const float cHi = invd(rti + 2);
    const float cHe = invd(rti + 1);
    const float cUi = invd(rtu + 2), cUe = invd(rtu + 1);
    const float cDi = invd(rtd + 2), cDe = invd(rtd + 1);

    const bool q0 = (q == 0), q5 = (q == 5);
    const bool hasU = (i > 0), hasD = (i < 23);
    const float cL0 = q0 ? 0.0f : cHi;
    const float cL1 = q0 ? cHe  : cHi;
    const float cR2 = q5 ? cHe  : cHi;
    const float cR3 = q5 ? 0.0f : cHi;
    const float vU = hasU ? 1.0f : 0.0f;
    const float vD = hasD ? 1.0f : 0.0f;
    const float cU0 = vU * (q0 ? cUe : cUi), cUm = vU * cUi, cU3 = vU * (q5 ? cUe : cUi);
    const float cD0 = vD * (q0 ? cDe : cDi), cDm = vD * cDi, cD3 = vD * (q5 ? cDe : cDi);

    const int upOff = hasU ? -24 : 0;              // clamped (coeff is 0 when clamped)
    const int dnOff = hasD ?  24 : 0;
    const int lfOff = q0 ? 0 : -1;
    const int rgOff = q5 ? 0 :  4;

    float a1[U_], a2[U_];

    #pragma unroll
    for (int u = 0; u < U_; u++) {
        const float* xc = xs + (slot * U_ + u) * NN + r * 4;
        const float4 wv = __ldg((const float4*)(w + (c0 + u) * NN + r * 4));
        const float4 up = *(const float4*)(xc + upOff);
        const float4 dn = *(const float4*)(xc + dnOff);
        const float  lf = xc[lfOff];
        const float  rg = xc[rgOff];
        const float4 c4 = ct[u];

        const float s0 = c4.x + cL0 * lf   + cHi * c4.y + cU0 * up.x + cD0 * dn.x;
        const float s1 = c4.y + cL1 * c4.x + cHi * c4.z + cUm * up.y + cDm * dn.y;
        const float s2 = c4.z + cHi * c4.y + cR2 * c4.w + cUm * up.z + cDm * dn.z;
        const float s3 = c4.w + cHi * c4.z + cR3 * rg   + cU3 * up.w + cD3 * dn.w;

        const float y0 = s0 * wv.x, y1 = s1 * wv.y, y2 = s2 * wv.z, y3 = s3 * wv.w;

        a1[u] = (y0 + y1) + (y2 + y3);
        a2[u] = (y0 * y0 + y1 * y1) + (y2 * y2 + y3 * y3);
        *(float4*)(out + off0 + u * NN) = make_float4(y0, y1, y2, y3);
    }

    #pragma unroll
    for (int u = 0; u < U_; u++) {
        ps1[(slot * U_ + u) * 144 + r] = a1[u];
        ps2[(slot * U_ + u) * 144 + r] = a2[u];
    }
    __syncthreads();
    // stage 1: 128 threads sum 9 consecutive partials (1152 = 128*9; 144 = 16*9
    // so groups never straddle an image)
    if (tid < 128) {
        float a = 0.f, b = 0.f;
        #pragma unroll
        for (int k = 0; k < 9; k++) { a += ps1[tid * 9 + k]; b += ps2[tid * 9 + k]; }
        qs1[tid] = a; qs2[tid] = b;
    }
    __syncthreads();
    // stage 2: one thread per image sums its 16 group partials
    if (tid < IPB) {
        float a = 0.f, b = 0.f;
        #pragma unroll
        for (int k = 0; k < 16; k++) { a += qs1[tid * 16 + k]; b += qs2[tid * 16 + k]; }
        const int bc = blockIdx.x * IPB + tid;
        const int bb = bc >> 9, cc = bc & (C_ - 1);
        g_psum[cc * B_ + bb] = a;
        g_psq [cc * B_ + bb] = b;
    }
}

// ---------------- finalize ----------------
__global__ void k_finalize(const float* __restrict__ gamma,
                           const float* __restrict__ beta) {
    const int c = threadIdx.x;   // 512 threads
    const float4* p1 = (const float4*)(g_psum + c * B_);
    const float4* p2 = (const float4*)(g_psq  + c * B_);
    float s1 = 0.f, s2 = 0.f;
    #pragma unroll
    for (int k = 0; k < 16; k++) {
        float4 a = p1[k], b = p2[k];
        s1 += (a.x + a.y) + (a.z + a.w);
        s2 += (b.x + b.y) + (b.z + b.w);
    }
    const float invn = 1.0f / 36864.0f;           // 1/(B*NN)
    const float mean = s1 * invn;
    const float var  = s2 * invn - mean * mean;
    const float sc = gamma[c] * rsqrtf(var + BN_EPS);
    g_scale[c] = sc;
    g_shift[c] = beta[c] - mean * sc;
}

// ---------------- Pass 2: streaming normalize + LeakyReLU ----------------
__global__ __launch_bounds__(TPB) void k_pass2(float* __restrict__ out) {
    const int tid   = threadIdx.x;
    const int slot2 = tid / 144;                  // 0 or 1
    const int r     = tid - 144 * slot2;
    const int base  = blockIdx.x * IPB;

    float4 v[U_];
    size_t off[U_];
    #pragma unroll
    for (int k = 0; k < U_; k++) {
        const int img = slot2 + 2 * k;            // 0..7 interleaved
        off[k] = (size_t)(base + img) * NN + r * 4;
        v[k] = *(const float4*)(out + off[k]);
    }
    #pragma unroll
    for (int k = 0; k < U_; k++) {
        const int cc = (base + slot2 + 2 * k) & (C_ - 1);
        const float sc = __ldg(&g_scale[cc]);
        const float sh = __ldg(&g_shift[cc]);
        float n0 = fmaf(v[k].x, sc, sh), n1 = fmaf(v[k].y, sc, sh);
        float n2 = fmaf(v[k].z, sc, sh), n3 = fmaf(v[k].w, sc, sh);
        n0 = (n0 >= 0.f) ? n0 : SLOPE * n0;
        n1 = (n1 >= 0.f) ? n1 : SLOPE * n1;
        n2 = (n2 >= 0.f) ? n2 : SLOPE * n2;
        n3 = (n3 >= 0.f) ? n3 : SLOPE * n3;
        *(float4*)(out + off[k]) = make_float4(n0, n1, n2, n3);
    }
}

extern "C" void kernel_launch(void* const* d_in, const int* in_sizes, int n_in,
                              void* d_out, int out_size) {
    const float* x     = (const float*)d_in[0];   // [64,512,24,24]
    // d_in[1] = adj (unused: grid structure exploited analytically)
    const float* w     = (const float*)d_in[2];   // [512,576]
    const float* gamma = (const float*)d_in[3];   // [512]
    const float* beta  = (const float*)d_in[4];   // [512]
    float* out = (float*)d_out;

    const int nblk = (B_ * C_) / IPB;             // 4096 blocks, 8 images each
    k_pass1<<<nblk, TPB>>>(x, w, out);
    k_finalize<<<1, C_>>>(gamma, beta);
    k_pass2<<<nblk, TPB>>>(out);
}

// round 9
// speedup vs baseline: 1.9636x; 1.2596x over previous
#include <cuda_runtime.h>

// Spatial GCN on a 24x24 grid: adj = D^-1 A + I (4-neighbor grid) => 5-point
// stencil with analytic 1/deg(neighbor) in {1/2, 1/3, 1/4}. Then elementwise
// weight, BatchNorm2d (batch stats), LeakyReLU(0.2).
//
// R9: ONE fused kernel, one block per channel. The whole channel (64 images,
// 144 KB) is staged in smem (pipelined loads), BN stats reduced in-block,
// stencil recomputed from resident smem for the normalize+write phase.
// Total DRAM traffic = read x once + write out once.

#define B_   64
#define C_   512
#define NN   576
#define BN_EPS 1e-4f
#define SLOPE  0.2f

#define TPB  576          // 18 warps; thread = (s, chunk r); 16 images/thread

__device__ __forceinline__ float invd(int d) {
    // d in {2,3,4}
    return d == 4 ? 0.25f : (d == 3 ? (1.0f / 3.0f) : 0.5f);
}

extern __shared__ float xs[];        // 64 * 576 floats = 147456 B

__global__ __launch_bounds__(TPB, 1)
void k_fused(const float* __restrict__ x,
             const float* __restrict__ w,
             const float* __restrict__ gamma,
             const float* __restrict__ beta,
             float* __restrict__ out) {
    __shared__ float red1[18], red2[18];
    __shared__ float s_scale, s_shift;

    const int t = threadIdx.x;
    const int s = t / 144;                        // 0..3
    const int r = t - 144 * s;                    // chunk 0..143
    const int i = r / 6;                          // row
    const int q = r - 6 * i;                      // chunk-in-row
    const int c = blockIdx.x;                     // channel

    // thread's images: b = 4*k + s, k = 0..15. group g covers k in [4g, 4g+3]
    // (= images [16g, 16g+15]).

    // ---- stencil coefficients (chunk-position only) ----
    const int rti = (i > 0) + (i < 23);
    const int rtu = (i > 1) + 1;                  // rowterm(i-1), valid iff i>0
    const int rtd = 1 + (i < 22);                 // rowterm(i+1), valid iff i<23
    const float cHi = invd(rti + 2);
    const float cHe = invd(rti + 1);
    const float cUi = invd(rtu + 2), cUe = invd(rtu + 1);
    const float cDi = invd(rtd + 2), cDe = invd(rtd + 1);

    const bool q0 = (q == 0), q5 = (q == 5);
    const bool hasU = (i > 0), hasD = (i < 23);
    const float cL0 = q0 ? 0.0f : cHi;
    const float cL1 = q0 ? cHe  : cHi;
    const float cR2 = q5 ? cHe  : cHi;
    const float cR3 = q5 ? 0.0f : cHi;
    const float vU = hasU ? 1.0f : 0.0f;
    const float vD = hasD ? 1.0f : 0.0f;
    const float cU0 = vU * (q0 ? cUe : cUi), cUm = vU * cUi, cU3 = vU * (q5 ? cUe : cUi);
    const float cD0 = vD * (q0 ? cDe : cDi), cDm = vD * cDi, cD3 = vD * (q5 ? cDe : cDi);

    const int upOff = hasU ? -24 : 0;             // clamped (coeff 0 when clamped)
    const int dnOff = hasD ?  24 : 0;
    const int lfOff = q0 ? 0 : -1;
    const int rgOff = q5 ? 0 :  4;

    // weight chunk: fixed for the whole block (one channel)
    const float4 wv = __ldg((const float4*)(w + c * NN + r * 4));

    // ---- pipelined stage + phase-1 stats ----
    float s1 = 0.0f, s2 = 0.0f;
    float4 buf[4];

    // prefetch group 0
    #pragma unroll
    for (int j = 0; j < 4; j++) {
        const int b = 4 * (0 * 4 + j) + s;
        buf[j] = *(const float4*)(x + ((size_t)b * C_ + c) * NN + r * 4);
    }

    #pragma unroll
    for (int g = 0; g < 4; g++) {
        // commit group g to smem
        #pragma unroll
        for (int j = 0; j < 4; j++) {
            const int b = 4 * (g * 4 + j) + s;
            *(float4*)(xs + b * NN + r * 4) = buf[j];
        }
        __syncthreads();
        // prefetch group g+1 (latency overlapped with compute below)
        if (g < 3) {
            #pragma unroll
            for (int j = 0; j < 4; j++) {
                const int b = 4 * ((g + 1) * 4 + j) + s;
                buf[j] = *(const float4*)(x + ((size_t)b * C_ + c) * NN + r * 4);
            }
        }
        // phase-1 stats on group g
        #pragma unroll
        for (int j = 0; j < 4; j++) {
            const int b = 4 * (g * 4 + j) + s;
            const float* xc = xs + b * NN + r * 4;
            const float4 c4 = *(const float4*)xc;
            const float4 up = *(const float4*)(xc + upOff);
            const float4 dn = *(const float4*)(xc + dnOff);
            const float  lf = xc[lfOff];
            const float  rg = xc[rgOff];

            const float t0 = c4.x + cL0 * lf   + cHi * c4.y + cU0 * up.x + cD0 * dn.x;
            const float t1 = c4.y + cL1 * c4.x + cHi * c4.z + cUm * up.y + cDm * dn.y;
            const float t2 = c4.z + cHi * c4.y + cR2 * c4.w + cUm * up.z + cDm * dn.z;
            const float t3 = c4.w + cHi * c4.z + cR3 * rg   + cU3 * up.w + cD3 * dn.w;

            const float y0 = t0 * wv.x, y1 = t1 * wv.y, y2 = t2 * wv.z, y3 = t3 * wv.w;
            s1 += (y0 + y1) + (y2 + y3);
            s2 += (y0 * y0 + y1 * y1) + (y2 * y2 + y3 * y3);
        }
        if (g < 3) __syncthreads();   // group g+1 smem commit must not race reads
    }

    // ---- block reduction (deterministic) ----
    const unsigned FULL = 0xFFFFFFFFu;
    #pragma unroll
    for (int o = 16; o; o >>= 1) {
        s1 += __shfl_down_sync(FULL, s1, o);
        s2 += __shfl_down_sync(FULL, s2, o);
    }
    const int wid = t >> 5, lane = t & 31;
    if (lane == 0) { red1[wid] = s1; red2[wid] = s2; }
    __syncthreads();
    if (wid == 0) {
        float a = (lane < 18) ? red1[lane] : 0.0f;
        float b = (lane < 18) ? red2[lane] : 0.0f;
        #pragma unroll
        for (int o = 16; o; o >>= 1) {
            a += __shfl_down_sync(FULL, a, o);
            b += __shfl_down_sync(FULL, b, o);
        }
        if (lane == 0) {
            const float invn = 1.0f / 36864.0f;   // 1/(B*NN)
            const float mean = a * invn;
            const float var  = b * invn - mean * mean;
            const float sc = gamma[c] * rsqrtf(var + BN_EPS);
            s_scale = sc;
            s_shift = beta[c] - mean * sc;
        }
    }
    __syncthreads();

    const float sc = s_scale, sh = s_shift;

    // ---- phase 2: recompute from resident smem, normalize, write ----
    #pragma unroll
    for (int k = 0; k < 16; k++) {
        const int b = 4 * k + s;
        const float* xc = xs + b * NN + r * 4;
        const float4 c4 = *(const float4*)xc;
        const float4 up = *(const float4*)(xc + upOff);
        const float4 dn = *(const float4*)(xc + dnOff);
        const float  lf = xc[lfOff];
        const float  rg = xc[rgOff];

        const float t0 = c4.x + cL0 * lf   + cHi * c4.y + cU0 * up.x + cD0 * dn.x;
        const float t1 = c4.y + cL1 * c4.x + cHi * c4.z + cUm * up.y + cDm * dn.y;
        const float t2 = c4.z + cHi * c4.y + cR2 * c4.w + cUm * up.z + cDm * dn.z;
        const float t3 = c4.w + cHi * c4.z + cR3 * rg   + cU3 * up.w + cD3 * dn.w;

        float n0 = fmaf(t0 * wv.x, sc, sh);
        float n1 = fmaf(t1 * wv.y, sc, sh);
        float n2 = fmaf(t2 * wv.z, sc, sh);
        float n3 = fmaf(t3 * wv.w, sc, sh);
        n0 = (n0 >= 0.f) ? n0 : SLOPE * n0;
        n1 = (n1 >= 0.f) ? n1 : SLOPE * n1;
        n2 = (n2 >= 0.f) ? n2 : SLOPE * n2;
        n3 = (n3 >= 0.f) ? n3 : SLOPE * n3;
        *(float4*)(out + ((size_t)b * C_ + c) * NN + r * 4) =
            make_float4(n0, n1, n2, n3);
    }
}

extern "C" void kernel_launch(void* const* d_in, const int* in_sizes, int n_in,
                              void* d_out, int out_size) {
    const float* x     = (const float*)d_in[0];   // [64,512,24,24]
    // d_in[1] = adj (unused: grid structure exploited analytically)
    const float* w     = (const float*)d_in[2];   // [512,576]
    const float* gamma = (const float*)d_in[3];   // [512]
    const float* beta  = (const float*)d_in[4];   // [512]
    float* out = (float*)d_out;

    const int smem = B_ * NN * (int)sizeof(float);          // 147456 B
    cudaFuncSetAttribute(k_fused, cudaFuncAttributeMaxDynamicSharedMemorySize, smem);
    k_fused<<<C_, TPB, smem>>>(x, w, gamma, beta, out);
}